// round 12
// baseline (speedup 1.0000x reference)
#include <cuda_runtime.h>

// Problem constants
#define NB   256          // windows (Bw)
#define NT   144          // tokens per window (N)
#define CD   384          // channel dim
#define NH   12           // heads
#define HD   32           // head dim
#define M_TOT (NB*NT)     // 36864 rows
#define QKV_N 1152
#define PIDX_LEN (NT*NT)  // 20736

// Scratch (static device allocations are the only legal scratch)
__device__ __align__(128) float g_q[NB*NH*NT*HD];
__device__ __align__(128) float g_k[NB*NH*NT*HD];
__device__ __align__(128) float g_v[NB*NH*NT*HD];
__device__ __align__(128) float g_ao[M_TOT*CD];

// ---------------------------------------------------------------------------
// Kernel 1: QKV projection.  C[36864,1152] = X[36864,384] @ W[384,1152] + b
// 128x128 block tile, BK=8, 8x8 per-thread microtile, 256 threads.
// Epilogue scatters into per-(window,head) Q/K/V layout; q gets *HD^-0.5.
// ---------------------------------------------------------------------------
__global__ __launch_bounds__(256) void qkv_gemm(const float* __restrict__ X,
                                                const float* __restrict__ W,
                                                const float* __restrict__ bias)
{
    __shared__ float As[8][128];
    __shared__ float Bs[8][128];
    const int tid = threadIdx.x;
    const int m0 = blockIdx.y * 128;
    const int n0 = blockIdx.x * 128;
    const int tx = tid & 15, ty = tid >> 4;
    const int a_row = tid >> 1, a_col = (tid & 1) * 4;
    const int b_row = tid >> 5, b_col = (tid & 31) * 4;

    float acc[8][8];
#pragma unroll
    for (int i = 0; i < 8; i++)
#pragma unroll
        for (int j = 0; j < 8; j++) acc[i][j] = 0.f;

    const float* Ap = X + (m0 + a_row) * CD + a_col;
    const float* Bp = W + b_row * QKV_N + n0 + b_col;

    for (int k0 = 0; k0 < CD; k0 += 8) {
        float4 av = *(const float4*)(Ap + k0);
        As[a_col+0][a_row] = av.x;
        As[a_col+1][a_row] = av.y;
        As[a_col+2][a_row] = av.z;
        As[a_col+3][a_row] = av.w;
        *(float4*)&Bs[b_row][b_col] = *(const float4*)(Bp + k0 * QKV_N);
        __syncthreads();
#pragma unroll
        for (int k = 0; k < 8; k++) {
            float ra[8], rb[8];
            *(float4*)&ra[0] = *(const float4*)&As[k][ty*8];
            *(float4*)&ra[4] = *(const float4*)&As[k][ty*8+4];
            *(float4*)&rb[0] = *(const float4*)&Bs[k][tx*8];
            *(float4*)&rb[4] = *(const float4*)&Bs[k][tx*8+4];
#pragma unroll
            for (int i = 0; i < 8; i++)
#pragma unroll
                for (int j = 0; j < 8; j++)
                    acc[i][j] += ra[i] * rb[j];
        }
        __syncthreads();
    }

    // Epilogue: whole 128-col tile lives inside one of q/k/v (384 = 3*128).
    const int which = n0 / CD;                          // 0=q, 1=k, 2=v
    float* dst = (which == 0) ? g_q : ((which == 1) ? g_k : g_v);
    const float sc = (which == 0) ? 0.17677669529663689f : 1.0f;  // 32^-0.5
    const int seg_col = (n0 - which * CD) + tx * 8;     // column within segment
    const int hh = seg_col >> 5;                        // head
    const int dd = seg_col & 31;                        // head-dim base (multiple of 8)
#pragma unroll
    for (int i = 0; i < 8; i++) {
        int m = m0 + ty * 8 + i;
        int b = m / NT, nn = m - b * NT;
        float* o = dst + (((b * NH + hh) * NT) + nn) * HD + dd;
#pragma unroll
        for (int j = 0; j < 8; j++)
            o[j] = (acc[i][j] + bias[n0 + tx * 8 + j]) * sc;
    }
}

// ---------------------------------------------------------------------------
// Kernel 2: attention per (window b, head h).
// One CTA per (b,h). 160 threads; threads 0..143 each own one query row.
// SMEM: score matrix S[144][145] (pad -> stride 17 banks, conflict-free) and
// a 144x32 K/V tile (K during phase 1, V during phase 2).
// Earth bias: bias(b,h,i,j) = table[ PI[ ((i*144+j)*8 + (b>>5)) % 20736 ], b&31, h ]
// (exact algebra of the reference tile->gather->reshape->transpose chain).
// ---------------------------------------------------------------------------
__global__ __launch_bounds__(160) void attn_kernel(const float* __restrict__ mask,
                                                   const float* __restrict__ table,
                                                   const int*   __restrict__ pidx)
{
    extern __shared__ float smem[];
    float* sS  = smem;                 // 144 * 145 floats
    float* sKV = smem + NT * 145;      // 144 * 32 floats

    const int tid = threadIdx.x;
    const int h = blockIdx.x;
    const int b = blockIdx.y;
    const int base = ((b * NH + h) * NT) * HD;

    // Load K tile cooperatively
    {
        const float4* src = (const float4*)(g_k + base);
        float4* dst = (float4*)sKV;
        for (int i = tid; i < NT * HD / 4; i += 160)
            dst[i] = src[i];
    }
    // Load this thread's q row
    float q[HD];
    if (tid < NT) {
        const float4* qp = (const float4*)(g_q + base + tid * HD);
#pragma unroll
        for (int d = 0; d < HD / 4; d++) {
            float4 t = qp[d];
            q[d*4+0] = t.x; q[d*4+1] = t.y; q[d*4+2] = t.z; q[d*4+3] = t.w;
        }
    }
    __syncthreads();

    float inv = 0.f;
    if (tid < NT) {
        const float* mrow = mask + (b & 7) * NT * NT + tid * NT;
        const float* bt   = table + (b & 31) * NH + h;   // + pi*384 per element
        float* srow = sS + tid * 145;
        // p = (i*144 + j)*8 + (b>>5), tracked incrementally mod 20736
        int p = (tid * NT * 8 + (b >> 5)) % PIDX_LEN;
        float mx = -1e30f;
        for (int j = 0; j < NT; j++) {
            const float* kr = sKV + j * HD;   // broadcast across threads
            float s0 = 0.f, s1 = 0.f, s2 = 0.f, s3 = 0.f;
#pragma unroll
            for (int d = 0; d < HD; d += 4) {
                s0 += q[d+0] * kr[d+0];
                s1 += q[d+1] * kr[d+1];
                s2 += q[d+2] * kr[d+2];
                s3 += q[d+3] * kr[d+3];
            }
            int pi = pidx[p];
            p += 8; if (p >= PIDX_LEN) p -= PIDX_LEN;
            float s = (s0 + s1) + (s2 + s3) + bt[pi * (32 * NH)] + mrow[j];
            mx = fmaxf(mx, s);
            srow[j] = s;
        }
        // softmax (unnormalized exp in smem; fold 1/sum into epilogue)
        float sum = 0.f;
        for (int j = 0; j < NT; j++) {
            float e = __expf(srow[j] - mx);
            srow[j] = e;
            sum += e;
        }
        inv = 1.0f / sum;
    }
    __syncthreads();

    // Swap V into the K/V tile
    {
        const float4* src = (const float4*)(g_v + base);
        float4* dst = (float4*)sKV;
        for (int i = tid; i < NT * HD / 4; i += 160)
            dst[i] = src[i];
    }
    __syncthreads();

    if (tid < NT) {
        const float* srow = sS + tid * 145;
        float acc[HD];
#pragma unroll
        for (int d = 0; d < HD; d++) acc[d] = 0.f;
        for (int j = 0; j < NT; j++) {
            float pj = srow[j];
            const float* vr = sKV + j * HD;  // broadcast
#pragma unroll
            for (int d = 0; d < HD; d++)
                acc[d] += pj * vr[d];
        }
        // write (b, n, h, d) layout so out_gemm reads dense rows
        float4* o4 = (float4*)(g_ao + (b * NT + tid) * CD + h * HD);
#pragma unroll
        for (int d = 0; d < HD / 4; d++) {
            float4 t;
            t.x = acc[d*4+0] * inv;
            t.y = acc[d*4+1] * inv;
            t.z = acc[d*4+2] * inv;
            t.w = acc[d*4+3] * inv;
            o4[d] = t;
        }
    }
}

// ---------------------------------------------------------------------------
// Kernel 3: output projection.  out[36864,384] = AO[36864,384] @ Wout[384,384] + b
// ---------------------------------------------------------------------------
__global__ __launch_bounds__(256) void out_gemm(const float* __restrict__ W,
                                                const float* __restrict__ bias,
                                                float* __restrict__ out)
{
    __shared__ float As[8][128];
    __shared__ float Bs[8][128];
    const int tid = threadIdx.x;
    const int m0 = blockIdx.y * 128;
    const int n0 = blockIdx.x * 128;
    const int tx = tid & 15, ty = tid >> 4;
    const int a_row = tid >> 1, a_col = (tid & 1) * 4;
    const int b_row = tid >> 5, b_col = (tid & 31) * 4;

    float acc[8][8];
#pragma unroll
    for (int i = 0; i < 8; i++)
#pragma unroll
        for (int j = 0; j < 8; j++) acc[i][j] = 0.f;

    const float* Ap = g_ao + (m0 + a_row) * CD + a_col;
    const float* Bp = W + b_row * CD + n0 + b_col;

    for (int k0 = 0; k0 < CD; k0 += 8) {
        float4 av = *(const float4*)(Ap + k0);
        As[a_col+0][a_row] = av.x;
        As[a_col+1][a_row] = av.y;
        As[a_col+2][a_row] = av.z;
        As[a_col+3][a_row] = av.w;
        *(float4*)&Bs[b_row][b_col] = *(const float4*)(Bp + k0 * CD);
        __syncthreads();
#pragma unroll
        for (int k = 0; k < 8; k++) {
            float ra[8], rb[8];
            *(float4*)&ra[0] = *(const float4*)&As[k][ty*8];
            *(float4*)&ra[4] = *(const float4*)&As[k][ty*8+4];
            *(float4*)&rb[0] = *(const float4*)&Bs[k][tx*8];
            *(float4*)&rb[4] = *(const float4*)&Bs[k][tx*8+4];
#pragma unroll
            for (int i = 0; i < 8; i++)
#pragma unroll
                for (int j = 0; j < 8; j++)
                    acc[i][j] += ra[i] * rb[j];
        }
        __syncthreads();
    }

    const int col0 = n0 + tx * 8;
#pragma unroll
    for (int i = 0; i < 8; i++) {
        int m = m0 + ty * 8 + i;
        float4* o4 = (float4*)(out + m * CD + col0);
        float4 v0, v1;
        v0.x = acc[i][0] + bias[col0+0];
        v0.y = acc[i][1] + bias[col0+1];
        v0.z = acc[i][2] + bias[col0+2];
        v0.w = acc[i][3] + bias[col0+3];
        v1.x = acc[i][4] + bias[col0+4];
        v1.y = acc[i][5] + bias[col0+5];
        v1.z = acc[i][6] + bias[col0+6];
        v1.w = acc[i][7] + bias[col0+7];
        o4[0] = v0;
        o4[1] = v1;
    }
}

// ---------------------------------------------------------------------------
extern "C" void kernel_launch(void* const* d_in, const int* in_sizes, int n_in,
                              void* d_out, int out_size)
{
    (void)in_sizes; (void)n_in; (void)out_size;
    const float* x     = (const float*)d_in[0];
    const float* mask  = (const float*)d_in[1];
    const float* w_qkv = (const float*)d_in[2];
    const float* b_qkv = (const float*)d_in[3];
    const float* w_out = (const float*)d_in[4];
    const float* b_out = (const float*)d_in[5];
    const float* table = (const float*)d_in[6];
    const int*   pidx  = (const int*)d_in[7];
    float* out = (float*)d_out;

    // QKV projection: grid (1152/128, 36864/128)
    qkv_gemm<<<dim3(9, 288), 256>>>(x, w_qkv, b_qkv);

    // Attention: one block per (head, window)
    const int shmem = (NT * 145 + NT * HD) * (int)sizeof(float);  // 101952 B
    cudaFuncSetAttribute(attn_kernel, cudaFuncAttributeMaxDynamicSharedMemorySize, shmem);
    attn_kernel<<<dim3(NH, NB), 160, shmem>>>(mask, table, pidx);

    // Output projection: grid (384/128, 36864/128)
    out_gemm<<<dim3(3, 288), 256>>>(w_out, b_out, out);
}

// round 13
// speedup vs baseline: 1.0437x; 1.0437x over previous
#include <cuda_runtime.h>

// Problem constants
#define NB   256          // windows (Bw)
#define NT   144          // tokens per window (N)
#define CD   384          // channel dim
#define NH   12           // heads
#define HD   32           // head dim
#define M_TOT (NB*NT)     // 36864 rows
#define QKV_N 1152
#define PIDX_LEN (NT*NT)  // 20736

// Scratch (static device allocations are the only legal scratch)
__device__ __align__(128) float g_q[NB*NH*NT*HD];
__device__ __align__(128) float g_k[NB*NH*NT*HD];
__device__ __align__(128) float g_v[NB*NH*NT*HD];
__device__ __align__(128) float g_ao[M_TOT*CD];

// ---------------------------------------------------------------------------
// Kernel 1: QKV projection.  C[36864,1152] = X[36864,384] @ W[384,1152] + b
// 128x128 block tile, BK=8, 8x8 per-thread microtile, 256 threads.
// Epilogue scatters into per-(window,head) Q/K/V layout; q gets *HD^-0.5.
// ---------------------------------------------------------------------------
__global__ __launch_bounds__(256) void qkv_gemm(const float* __restrict__ X,
                                                const float* __restrict__ W,
                                                const float* __restrict__ bias)
{
    __shared__ float As[8][128];
    __shared__ float Bs[8][128];
    const int tid = threadIdx.x;
    const int m0 = blockIdx.y * 128;
    const int n0 = blockIdx.x * 128;
    const int tx = tid & 15, ty = tid >> 4;
    const int a_row = tid >> 1, a_col = (tid & 1) * 4;
    const int b_row = tid >> 5, b_col = (tid & 31) * 4;

    float acc[8][8];
#pragma unroll
    for (int i = 0; i < 8; i++)
#pragma unroll
        for (int j = 0; j < 8; j++) acc[i][j] = 0.f;

    const float* Ap = X + (m0 + a_row) * CD + a_col;
    const float* Bp = W + b_row * QKV_N + n0 + b_col;

    for (int k0 = 0; k0 < CD; k0 += 8) {
        float4 av = *(const float4*)(Ap + k0);
        As[a_col+0][a_row] = av.x;
        As[a_col+1][a_row] = av.y;
        As[a_col+2][a_row] = av.z;
        As[a_col+3][a_row] = av.w;
        *(float4*)&Bs[b_row][b_col] = *(const float4*)(Bp + k0 * QKV_N);
        __syncthreads();
#pragma unroll
        for (int k = 0; k < 8; k++) {
            float ra[8], rb[8];
            *(float4*)&ra[0] = *(const float4*)&As[k][ty*8];
            *(float4*)&ra[4] = *(const float4*)&As[k][ty*8+4];
            *(float4*)&rb[0] = *(const float4*)&Bs[k][tx*8];
            *(float4*)&rb[4] = *(const float4*)&Bs[k][tx*8+4];
#pragma unroll
            for (int i = 0; i < 8; i++)
#pragma unroll
                for (int j = 0; j < 8; j++)
                    acc[i][j] += ra[i] * rb[j];
        }
        __syncthreads();
    }

    // Epilogue: whole 128-col tile lives inside one of q/k/v (384 = 3*128).
    const int which = n0 / CD;                          // 0=q, 1=k, 2=v
    float* dst = (which == 0) ? g_q : ((which == 1) ? g_k : g_v);
    const float sc = (which == 0) ? 0.17677669529663689f : 1.0f;  // 32^-0.5
    const int seg_col = (n0 - which * CD) + tx * 8;     // column within segment
    const int hh = seg_col >> 5;                        // head
    const int dd = seg_col & 31;                        // head-dim base (multiple of 8)
#pragma unroll
    for (int i = 0; i < 8; i++) {
        int m = m0 + ty * 8 + i;
        int b = m / NT, nn = m - b * NT;
        float* o = dst + (((b * NH + hh) * NT) + nn) * HD + dd;
#pragma unroll
        for (int j = 0; j < 8; j++)
            o[j] = (acc[i][j] + bias[n0 + tx * 8 + j]) * sc;
    }
}

// ---------------------------------------------------------------------------
// Kernel 2: attention per (window b, head h).
// One CTA per (b,h). 160 threads; threads 0..143 each own one query row.
// SMEM: score matrix S[144][145] (pad -> stride 17 banks, conflict-free) and
// a 144x32 K/V tile (K during phase 1, V during phase 2).
// Earth bias: bias(b,h,i,j) = table[ PI[ ((i*144+j)*8 + (b>>5)) % 20736 ], b&31, h ]
// (exact algebra of the reference tile->gather->reshape->transpose chain).
// ---------------------------------------------------------------------------
__global__ __launch_bounds__(160) void attn_kernel(const float* __restrict__ mask,
                                                   const float* __restrict__ table,
                                                   const int*   __restrict__ pidx)
{
    extern __shared__ float smem[];
    float* sS  = smem;                 // 144 * 145 floats
    float* sKV = smem + NT * 145;      // 144 * 32 floats

    const int tid = threadIdx.x;
    const int h = blockIdx.x;
    const int b = blockIdx.y;
    const int base = ((b * NH + h) * NT) * HD;

    // Load K tile cooperatively
    {
        const float4* src = (const float4*)(g_k + base);
        float4* dst = (float4*)sKV;
        for (int i = tid; i < NT * HD / 4; i += 160)
            dst[i] = src[i];
    }
    // Load this thread's q row
    float q[HD];
    if (tid < NT) {
        const float4* qp = (const float4*)(g_q + base + tid * HD);
#pragma unroll
        for (int d = 0; d < HD / 4; d++) {
            float4 t = qp[d];
            q[d*4+0] = t.x; q[d*4+1] = t.y; q[d*4+2] = t.z; q[d*4+3] = t.w;
        }
    }
    __syncthreads();

    float inv = 0.f;
    if (tid < NT) {
        const float* mrow = mask + (b & 7) * NT * NT + tid * NT;
        const float* bt   = table + (b & 31) * NH + h;   // + pi*384 per element
        float* srow = sS + tid * 145;
        // p = (i*144 + j)*8 + (b>>5), tracked incrementally mod 20736
        int p = (tid * NT * 8 + (b >> 5)) % PIDX_LEN;
        float mx = -1e30f;
        for (int j = 0; j < NT; j++) {
            const float* kr = sKV + j * HD;   // broadcast across threads
            float s0 = 0.f, s1 = 0.f, s2 = 0.f, s3 = 0.f;
#pragma unroll
            for (int d = 0; d < HD; d += 4) {
                s0 += q[d+0] * kr[d+0];
                s1 += q[d+1] * kr[d+1];
                s2 += q[d+2] * kr[d+2];
                s3 += q[d+3] * kr[d+3];
            }
            int pi = pidx[p];
            p += 8; if (p >= PIDX_LEN) p -= PIDX_LEN;
            float s = (s0 + s1) + (s2 + s3) + bt[pi * (32 * NH)] + mrow[j];
            mx = fmaxf(mx, s);
            srow[j] = s;
        }
        // softmax (unnormalized exp in smem; fold 1/sum into epilogue)
        float sum = 0.f;
        for (int j = 0; j < NT; j++) {
            float e = __expf(srow[j] - mx);
            srow[j] = e;
            sum += e;
        }
        inv = 1.0f / sum;
    }
    __syncthreads();

    // Swap V into the K/V tile
    {
        const float4* src = (const float4*)(g_v + base);
        float4* dst = (float4*)sKV;
        for (int i = tid; i < NT * HD / 4; i += 160)
            dst[i] = src[i];
    }
    __syncthreads();

    if (tid < NT) {
        const float* srow = sS + tid * 145;
        float acc[HD];
#pragma unroll
        for (int d = 0; d < HD; d++) acc[d] = 0.f;
        for (int j = 0; j < NT; j++) {
            float pj = srow[j];
            const float* vr = sKV + j * HD;  // broadcast
#pragma unroll
            for (int d = 0; d < HD; d++)
                acc[d] += pj * vr[d];
        }
        // write (b, n, h, d) layout so out_gemm reads dense rows
        float4* o4 = (float4*)(g_ao + (b * NT + tid) * CD + h * HD);
#pragma unroll
        for (int d = 0; d < HD / 4; d++) {
            float4 t;
            t.x = acc[d*4+0] * inv;
            t.y = acc[d*4+1] * inv;
            t.z = acc[d*4+2] * inv;
            t.w = acc[d*4+3] * inv;
            o4[d] = t;
        }
    }
}

// ---------------------------------------------------------------------------
// Kernel 3: output projection.  out[36864,384] = AO[36864,384] @ Wout[384,384] + b
// ---------------------------------------------------------------------------
__global__ __launch_bounds__(256) void out_gemm(const float* __restrict__ W,
                                                const float* __restrict__ bias,
                                                float* __restrict__ out)
{
    __shared__ float As[8][128];
    __shared__ float Bs[8][128];
    const int tid = threadIdx.x;
    const int m0 = blockIdx.y * 128;
    const int n0 = blockIdx.x * 128;
    const int tx = tid & 15, ty = tid >> 4;
    const int a_row = tid >> 1, a_col = (tid & 1) * 4;
    const int b_row = tid >> 5, b_col = (tid & 31) * 4;

    float acc[8][8];
#pragma unroll
    for (int i = 0; i < 8; i++)
#pragma unroll
        for (int j = 0; j < 8; j++) acc[i][j] = 0.f;

    const float* Ap = g_ao + (m0 + a_row) * CD + a_col;
    const float* Bp = W + b_row * CD + n0 + b_col;

    for (int k0 = 0; k0 < CD; k0 += 8) {
        float4 av = *(const float4*)(Ap + k0);
        As[a_col+0][a_row] = av.x;
        As[a_col+1][a_row] = av.y;
        As[a_col+2][a_row] = av.z;
        As[a_col+3][a_row] = av.w;
        *(float4*)&Bs[b_row][b_col] = *(const float4*)(Bp + k0 * CD);
        __syncthreads();
#pragma unroll
        for (int k = 0; k < 8; k++) {
            float ra[8], rb[8];
            *(float4*)&ra[0] = *(const float4*)&As[k][ty*8];
            *(float4*)&ra[4] = *(const float4*)&As[k][ty*8+4];
            *(float4*)&rb[0] = *(const float4*)&Bs[k][tx*8];
            *(float4*)&rb[4] = *(const float4*)&Bs[k][tx*8+4];
#pragma unroll
            for (int i = 0; i < 8; i++)
#pragma unroll
                for (int j = 0; j < 8; j++)
                    acc[i][j] += ra[i] * rb[j];
        }
        __syncthreads();
    }

    const int col0 = n0 + tx * 8;
#pragma unroll
    for (int i = 0; i < 8; i++) {
        int m = m0 + ty * 8 + i;
        float4* o4 = (float4*)(out + m * CD + col0);
        float4 v0, v1;
        v0.x = acc[i][0] + bias[col0+0];
        v0.y = acc[i][1] + bias[col0+1];
        v0.z = acc[i][2] + bias[col0+2];
        v0.w = acc[i][3] + bias[col0+3];
        v1.x = acc[i][4] + bias[col0+4];
        v1.y = acc[i][5] + bias[col0+5];
        v1.z = acc[i][6] + bias[col0+6];
        v1.w = acc[i][7] + bias[col0+7];
        o4[0] = v0;
        o4[1] = v1;
    }
}

// ---------------------------------------------------------------------------
extern "C" void kernel_launch(void* const* d_in, const int* in_sizes, int n_in,
                              void* d_out, int out_size)
{
    (void)in_sizes; (void)n_in; (void)out_size;
    const float* x     = (const float*)d_in[0];
    const float* mask  = (const float*)d_in[1];
    const float* w_qkv = (const float*)d_in[2];
    const float* b_qkv = (const float*)d_in[3];
    const float* w_out = (const float*)d_in[4];
    const float* b_out = (const float*)d_in[5];
    const float* table = (const float*)d_in[6];
    const int*   pidx  = (const int*)d_in[7];
    float* out = (float*)d_out;

    // QKV projection: grid (1152/128, 36864/128)
    qkv_gemm<<<dim3(9, 288), 256>>>(x, w_qkv, b_qkv);

    // Attention: one block per (head, window)
    const int shmem = (NT * 145 + NT * HD) * (int)sizeof(float);  // 101952 B
    cudaFuncSetAttribute(attn_kernel, cudaFuncAttributeMaxDynamicSharedMemorySize, shmem);
    attn_kernel<<<dim3(NH, NB), 160, shmem>>>(mask, table, pidx);

    // Output projection: grid (384/128, 36864/128)
    out_gemm<<<dim3(3, 288), 256>>>(w_out, b_out, out);
}

// round 14
// speedup vs baseline: 1.0500x; 1.0060x over previous
#include <cuda_runtime.h>

// Problem constants
#define NB   256          // windows (Bw)
#define NT   144          // tokens per window (N)
#define CD   384          // channel dim
#define NH   12           // heads
#define HD   32           // head dim
#define M_TOT (NB*NT)     // 36864 rows
#define QKV_N 1152
#define PIDX_LEN (NT*NT)  // 20736

// Scratch (static device allocations are the only legal scratch)
__device__ __align__(128) float g_q[NB*NH*NT*HD];
__device__ __align__(128) float g_k[NB*NH*NT*HD];
__device__ __align__(128) float g_v[NB*NH*NT*HD];
__device__ __align__(128) float g_ao[M_TOT*CD];

// ---------------------------------------------------------------------------
// Kernel 1: QKV projection.  C[36864,1152] = X[36864,384] @ W[384,1152] + b
// 128x128 block tile, BK=8, 8x8 per-thread microtile, 256 threads.
// Epilogue scatters into per-(window,head) Q/K/V layout; q gets *HD^-0.5.
// ---------------------------------------------------------------------------
__global__ __launch_bounds__(256) void qkv_gemm(const float* __restrict__ X,
                                                const float* __restrict__ W,
                                                const float* __restrict__ bias)
{
    __shared__ float As[8][128];
    __shared__ float Bs[8][128];
    const int tid = threadIdx.x;
    const int m0 = blockIdx.y * 128;
    const int n0 = blockIdx.x * 128;
    const int tx = tid & 15, ty = tid >> 4;
    const int a_row = tid >> 1, a_col = (tid & 1) * 4;
    const int b_row = tid >> 5, b_col = (tid & 31) * 4;

    float acc[8][8];
#pragma unroll
    for (int i = 0; i < 8; i++)
#pragma unroll
        for (int j = 0; j < 8; j++) acc[i][j] = 0.f;

    const float* Ap = X + (m0 + a_row) * CD + a_col;
    const float* Bp = W + b_row * QKV_N + n0 + b_col;

    for (int k0 = 0; k0 < CD; k0 += 8) {
        float4 av = *(const float4*)(Ap + k0);
        As[a_col+0][a_row] = av.x;
        As[a_col+1][a_row] = av.y;
        As[a_col+2][a_row] = av.z;
        As[a_col+3][a_row] = av.w;
        *(float4*)&Bs[b_row][b_col] = *(const float4*)(Bp + k0 * QKV_N);
        __syncthreads();
#pragma unroll
        for (int k = 0; k < 8; k++) {
            float ra[8], rb[8];
            *(float4*)&ra[0] = *(const float4*)&As[k][ty*8];
            *(float4*)&ra[4] = *(const float4*)&As[k][ty*8+4];
            *(float4*)&rb[0] = *(const float4*)&Bs[k][tx*8];
            *(float4*)&rb[4] = *(const float4*)&Bs[k][tx*8+4];
#pragma unroll
            for (int i = 0; i < 8; i++)
#pragma unroll
                for (int j = 0; j < 8; j++)
                    acc[i][j] += ra[i] * rb[j];
        }
        __syncthreads();
    }

    // Epilogue: whole 128-col tile lives inside one of q/k/v (384 = 3*128).
    const int which = n0 / CD;                          // 0=q, 1=k, 2=v
    float* dst = (which == 0) ? g_q : ((which == 1) ? g_k : g_v);
    const float sc = (which == 0) ? 0.17677669529663689f : 1.0f;  // 32^-0.5
    const int seg_col = (n0 - which * CD) + tx * 8;     // column within segment
    const int hh = seg_col >> 5;                        // head
    const int dd = seg_col & 31;                        // head-dim base (multiple of 8)
#pragma unroll
    for (int i = 0; i < 8; i++) {
        int m = m0 + ty * 8 + i;
        int b = m / NT, nn = m - b * NT;
        float* o = dst + (((b * NH + hh) * NT) + nn) * HD + dd;
#pragma unroll
        for (int j = 0; j < 8; j++)
            o[j] = (acc[i][j] + bias[n0 + tx * 8 + j]) * sc;
    }
}

// ---------------------------------------------------------------------------
// Kernel 2: attention per (window b, head h).
// One CTA per (b,h). 160 threads; threads 0..143 each own one query row.
// SMEM: score matrix S[144][145] (pad -> stride 17 banks, conflict-free) and
// a 144x32 K/V tile (K during phase 1, V during phase 2).
// Earth bias: bias(b,h,i,j) = table[ PI[ ((i*144+j)*8 + (b>>5)) % 20736 ], b&31, h ]
// (exact algebra of the reference tile->gather->reshape->transpose chain).
// ---------------------------------------------------------------------------
__global__ __launch_bounds__(160) void attn_kernel(const float* __restrict__ mask,
                                                   const float* __restrict__ table,
                                                   const int*   __restrict__ pidx)
{
    extern __shared__ float smem[];
    float* sS  = smem;                 // 144 * 145 floats
    float* sKV = smem + NT * 145;      // 144 * 32 floats

    const int tid = threadIdx.x;
    const int h = blockIdx.x;
    const int b = blockIdx.y;
    const int base = ((b * NH + h) * NT) * HD;

    // Load K tile cooperatively
    {
        const float4* src = (const float4*)(g_k + base);
        float4* dst = (float4*)sKV;
        for (int i = tid; i < NT * HD / 4; i += 160)
            dst[i] = src[i];
    }
    // Load this thread's q row
    float q[HD];
    if (tid < NT) {
        const float4* qp = (const float4*)(g_q + base + tid * HD);
#pragma unroll
        for (int d = 0; d < HD / 4; d++) {
            float4 t = qp[d];
            q[d*4+0] = t.x; q[d*4+1] = t.y; q[d*4+2] = t.z; q[d*4+3] = t.w;
        }
    }
    __syncthreads();

    float inv = 0.f;
    if (tid < NT) {
        const float* mrow = mask + (b & 7) * NT * NT + tid * NT;
        const float* bt   = table + (b & 31) * NH + h;   // + pi*384 per element
        float* srow = sS + tid * 145;
        // p = (i*144 + j)*8 + (b>>5), tracked incrementally mod 20736
        int p = (tid * NT * 8 + (b >> 5)) % PIDX_LEN;
        float mx = -1e30f;
        for (int j = 0; j < NT; j++) {
            const float* kr = sKV + j * HD;   // broadcast across threads
            float s0 = 0.f, s1 = 0.f, s2 = 0.f, s3 = 0.f;
#pragma unroll
            for (int d = 0; d < HD; d += 4) {
                s0 += q[d+0] * kr[d+0];
                s1 += q[d+1] * kr[d+1];
                s2 += q[d+2] * kr[d+2];
                s3 += q[d+3] * kr[d+3];
            }
            int pi = pidx[p];
            p += 8; if (p >= PIDX_LEN) p -= PIDX_LEN;
            float s = (s0 + s1) + (s2 + s3) + bt[pi * (32 * NH)] + mrow[j];
            mx = fmaxf(mx, s);
            srow[j] = s;
        }
        // softmax (unnormalized exp in smem; fold 1/sum into epilogue)
        float sum = 0.f;
        for (int j = 0; j < NT; j++) {
            float e = __expf(srow[j] - mx);
            srow[j] = e;
            sum += e;
        }
        inv = 1.0f / sum;
    }
    __syncthreads();

    // Swap V into the K/V tile
    {
        const float4* src = (const float4*)(g_v + base);
        float4* dst = (float4*)sKV;
        for (int i = tid; i < NT * HD / 4; i += 160)
            dst[i] = src[i];
    }
    __syncthreads();

    if (tid < NT) {
        const float* srow = sS + tid * 145;
        float acc[HD];
#pragma unroll
        for (int d = 0; d < HD; d++) acc[d] = 0.f;
        for (int j = 0; j < NT; j++) {
            float pj = srow[j];
            const float* vr = sKV + j * HD;  // broadcast
#pragma unroll
            for (int d = 0; d < HD; d++)
                acc[d] += pj * vr[d];
        }
        // write (b, n, h, d) layout so out_gemm reads dense rows
        float4* o4 = (float4*)(g_ao + (b * NT + tid) * CD + h * HD);
#pragma unroll
        for (int d = 0; d < HD / 4; d++) {
            float4 t;
            t.x = acc[d*4+0] * inv;
            t.y = acc[d*4+1] * inv;
            t.z = acc[d*4+2] * inv;
            t.w = acc[d*4+3] * inv;
            o4[d] = t;
        }
    }
}

// ---------------------------------------------------------------------------
// Kernel 3: output projection.  out[36864,384] = AO[36864,384] @ Wout[384,384] + b
// ---------------------------------------------------------------------------
__global__ __launch_bounds__(256) void out_gemm(const float* __restrict__ W,
                                                const float* __restrict__ bias,
                                                float* __restrict__ out)
{
    __shared__ float As[8][128];
    __shared__ float Bs[8][128];
    const int tid = threadIdx.x;
    const int m0 = blockIdx.y * 128;
    const int n0 = blockIdx.x * 128;
    const int tx = tid & 15, ty = tid >> 4;
    const int a_row = tid >> 1, a_col = (tid & 1) * 4;
    const int b_row = tid >> 5, b_col = (tid & 31) * 4;

    float acc[8][8];
#pragma unroll
    for (int i = 0; i < 8; i++)
#pragma unroll
        for (int j = 0; j < 8; j++) acc[i][j] = 0.f;

    const float* Ap = g_ao + (m0 + a_row) * CD + a_col;
    const float* Bp = W + b_row * CD + n0 + b_col;

    for (int k0 = 0; k0 < CD; k0 += 8) {
        float4 av = *(const float4*)(Ap + k0);
        As[a_col+0][a_row] = av.x;
        As[a_col+1][a_row] = av.y;
        As[a_col+2][a_row] = av.z;
        As[a_col+3][a_row] = av.w;
        *(float4*)&Bs[b_row][b_col] = *(const float4*)(Bp + k0 * CD);
        __syncthreads();
#pragma unroll
        for (int k = 0; k < 8; k++) {
            float ra[8], rb[8];
            *(float4*)&ra[0] = *(const float4*)&As[k][ty*8];
            *(float4*)&ra[4] = *(const float4*)&As[k][ty*8+4];
            *(float4*)&rb[0] = *(const float4*)&Bs[k][tx*8];
            *(float4*)&rb[4] = *(const float4*)&Bs[k][tx*8+4];
#pragma unroll
            for (int i = 0; i < 8; i++)
#pragma unroll
                for (int j = 0; j < 8; j++)
                    acc[i][j] += ra[i] * rb[j];
        }
        __syncthreads();
    }

    const int col0 = n0 + tx * 8;
#pragma unroll
    for (int i = 0; i < 8; i++) {
        int m = m0 + ty * 8 + i;
        float4* o4 = (float4*)(out + m * CD + col0);
        float4 v0, v1;
        v0.x = acc[i][0] + bias[col0+0];
        v0.y = acc[i][1] + bias[col0+1];
        v0.z = acc[i][2] + bias[col0+2];
        v0.w = acc[i][3] + bias[col0+3];
        v1.x = acc[i][4] + bias[col0+4];
        v1.y = acc[i][5] + bias[col0+5];
        v1.z = acc[i][6] + bias[col0+6];
        v1.w = acc[i][7] + bias[col0+7];
        o4[0] = v0;
        o4[1] = v1;
    }
}

// ---------------------------------------------------------------------------
extern "C" void kernel_launch(void* const* d_in, const int* in_sizes, int n_in,
                              void* d_out, int out_size)
{
    (void)in_sizes; (void)n_in; (void)out_size;
    const float* x     = (const float*)d_in[0];
    const float* mask  = (const float*)d_in[1];
    const float* w_qkv = (const float*)d_in[2];
    const float* b_qkv = (const float*)d_in[3];
    const float* w_out = (const float*)d_in[4];
    const float* b_out = (const float*)d_in[5];
    const float* table = (const float*)d_in[6];
    const int*   pidx  = (const int*)d_in[7];
    float* out = (float*)d_out;

    // QKV projection: grid (1152/128, 36864/128)
    qkv_gemm<<<dim3(9, 288), 256>>>(x, w_qkv, b_qkv);

    // Attention: one block per (head, window)
    const int shmem = (NT * 145 + NT * HD) * (int)sizeof(float);  // 101952 B
    cudaFuncSetAttribute(attn_kernel, cudaFuncAttributeMaxDynamicSharedMemorySize, shmem);
    attn_kernel<<<dim3(NH, NB), 160, shmem>>>(mask, table, pidx);

    // Output projection: grid (384/128, 36864/128)
    out_gemm<<<dim3(3, 288), 256>>>(w_out, b_out, out);
}

// round 15
// speedup vs baseline: 1.1867x; 1.1302x over previous
#include <cuda_runtime.h>

// Problem constants
#define NB   256          // windows (Bw)
#define NT   144          // tokens per window (N)
#define CD   384          // channel dim
#define NH   12           // heads
#define HD   32           // head dim
#define M_TOT (NB*NT)     // 36864 rows
#define QKV_N 1152
#define PIDX_LEN (NT*NT)  // 20736

// Scratch (static device allocations are the only legal scratch)
__device__ __align__(128) float g_q[NB*NH*NT*HD];
__device__ __align__(128) float g_k[NB*NH*NT*HD];
__device__ __align__(128) float g_v[NB*NH*NT*HD];
__device__ __align__(128) float g_ao[M_TOT*CD];
__device__ __align__(128) short g_pi16[8 * PIDX_LEN];   // per-r gathered position index

// ---------------------------------------------------------------------------
// Kernel 0: precompute g_pi16[r][ij] = pidx[(ij*8 + r) % 20736]  (fits int16)
// ---------------------------------------------------------------------------
__global__ void pi_precompute(const int* __restrict__ pidx)
{
    int idx = blockIdx.x * blockDim.x + threadIdx.x;
    if (idx >= 8 * PIDX_LEN) return;
    int r = idx / PIDX_LEN;
    int ij = idx - r * PIDX_LEN;
    int p = (ij * 8 + r) % PIDX_LEN;
    g_pi16[idx] = (short)pidx[p];
}

// ---------------------------------------------------------------------------
// Kernel 1: QKV projection.  C[36864,1152] = X[36864,384] @ W[384,1152] + b
// 128x128 block tile, BK=8 double-buffered, 8x8 per-thread microtile, 256 thr.
// Epilogue scatters into per-(window,head) Q/K/V layout; q gets *HD^-0.5.
// ---------------------------------------------------------------------------
__global__ __launch_bounds__(256) void qkv_gemm(const float* __restrict__ X,
                                                const float* __restrict__ W,
                                                const float* __restrict__ bias)
{
    __shared__ float As[2][8][128];
    __shared__ float Bs[2][8][128];
    const int tid = threadIdx.x;
    const int m0 = blockIdx.y * 128;
    const int n0 = blockIdx.x * 128;
    const int tx = tid & 15, ty = tid >> 4;
    const int a_row = tid >> 1, a_col = (tid & 1) * 4;
    const int b_row = tid >> 5, b_col = (tid & 31) * 4;

    float acc[8][8];
#pragma unroll
    for (int i = 0; i < 8; i++)
#pragma unroll
        for (int j = 0; j < 8; j++) acc[i][j] = 0.f;

    const float* Ap = X + (m0 + a_row) * CD + a_col;
    const float* Bp = W + b_row * QKV_N + n0 + b_col;

    // preload k0 = 0
    {
        float4 av = *(const float4*)(Ap);
        float4 bv = *(const float4*)(Bp);
        As[0][a_col+0][a_row] = av.x;
        As[0][a_col+1][a_row] = av.y;
        As[0][a_col+2][a_row] = av.z;
        As[0][a_col+3][a_row] = av.w;
        *(float4*)&Bs[0][b_row][b_col] = bv;
    }
    __syncthreads();

    int cur = 0;
    for (int k0 = 0; k0 < CD; k0 += 8) {
        float4 an, bn;
        const bool has_next = (k0 + 8 < CD);
        if (has_next) {
            an = *(const float4*)(Ap + (k0 + 8));
            bn = *(const float4*)(Bp + (k0 + 8) * QKV_N);
        }
#pragma unroll
        for (int k = 0; k < 8; k++) {
            float ra[8], rb[8];
            *(float4*)&ra[0] = *(const float4*)&As[cur][k][ty*8];
            *(float4*)&ra[4] = *(const float4*)&As[cur][k][ty*8+4];
            *(float4*)&rb[0] = *(const float4*)&Bs[cur][k][tx*8];
            *(float4*)&rb[4] = *(const float4*)&Bs[cur][k][tx*8+4];
#pragma unroll
            for (int i = 0; i < 8; i++)
#pragma unroll
                for (int j = 0; j < 8; j++)
                    acc[i][j] += ra[i] * rb[j];
        }
        if (has_next) {
            int nxt = cur ^ 1;
            As[nxt][a_col+0][a_row] = an.x;
            As[nxt][a_col+1][a_row] = an.y;
            As[nxt][a_col+2][a_row] = an.z;
            As[nxt][a_col+3][a_row] = an.w;
            *(float4*)&Bs[nxt][b_row][b_col] = bn;
        }
        __syncthreads();
        cur ^= 1;
    }

    // Epilogue: whole 128-col tile lives inside one of q/k/v (384 = 3*128).
    const int which = n0 / CD;                          // 0=q, 1=k, 2=v
    float* dst = (which == 0) ? g_q : ((which == 1) ? g_k : g_v);
    const float sc = (which == 0) ? 0.17677669529663689f : 1.0f;  // 32^-0.5
    const int seg_col = (n0 - which * CD) + tx * 8;     // column within segment
    const int hh = seg_col >> 5;                        // head
    const int dd = seg_col & 31;                        // head-dim base (multiple of 8)
#pragma unroll
    for (int i = 0; i < 8; i++) {
        int m = m0 + ty * 8 + i;
        int b = m / NT, nn = m - b * NT;
        float* o = dst + (((b * NH + hh) * NT) + nn) * HD + dd;
#pragma unroll
        for (int j = 0; j < 8; j++)
            o[j] = (acc[i][j] + bias[n0 + tx * 8 + j]) * sc;
    }
}

// ---------------------------------------------------------------------------
// Kernel 2: attention per (window b, head h).
// One CTA per (b,h). 160 threads; threads 0..143 each own one query row.
// Phase A (cooperative fill): sS[i][j] = mask(b&7,i,j) + table[pi(r,ij)][b&31][h]
//   - mask + g_pi16 loads are coalesced; table gather has ~130-deep MLP/thread.
// Phase B: per-row QK dot (K broadcast from smem) + running max.
// Phase C: softmax; Phase D: PV from smem-resident V.
// sS stride 145 -> bank (tid*17+j)%32, conflict-free scalar access.
// ---------------------------------------------------------------------------
__global__ __launch_bounds__(160) void attn_kernel(const float* __restrict__ mask,
                                                   const float* __restrict__ table)
{
    extern __shared__ float smem[];
    float* sS  = smem;                 // 144 * 145 floats
    float* sKV = smem + NT * 145;      // 144 * 32 floats

    const int tid = threadIdx.x;
    const int h = blockIdx.x;
    const int b = blockIdx.y;
    const int base = ((b * NH + h) * NT) * HD;

    // Load K tile cooperatively
    {
        const float4* src = (const float4*)(g_k + base);
        float4* dst = (float4*)sKV;
        for (int i = tid; i < NT * HD / 4; i += 160)
            dst[i] = src[i];
    }

    // Cooperative fill: mask + earth bias into sS
    {
        const int cc = (b & 31) * NH + h;
        const float* mbase = mask + (b & 7) * PIDX_LEN;
        const short* pis = g_pi16 + (b >> 5) * PIDX_LEN;
        for (int idx = tid; idx < PIDX_LEN; idx += 160) {
            int i = idx / NT;
            int j = idx - i * NT;
            int pi = (int)pis[idx];
            sS[i * 145 + j] = mbase[idx] + __ldg(table + pi * (32 * NH) + cc);
        }
    }

    // Load this thread's q row
    float q[HD];
    if (tid < NT) {
        const float4* qp = (const float4*)(g_q + base + tid * HD);
#pragma unroll
        for (int d = 0; d < HD / 4; d++) {
            float4 t = qp[d];
            q[d*4+0] = t.x; q[d*4+1] = t.y; q[d*4+2] = t.z; q[d*4+3] = t.w;
        }
    }
    __syncthreads();

    float inv = 0.f;
    if (tid < NT) {
        float* srow = sS + tid * 145;
        float mx = -1e30f;
        for (int j = 0; j < NT; j++) {
            const float* kr = sKV + j * HD;   // broadcast across threads
            float s0 = 0.f, s1 = 0.f, s2 = 0.f, s3 = 0.f;
#pragma unroll
            for (int d = 0; d < HD; d += 4) {
                s0 += q[d+0] * kr[d+0];
                s1 += q[d+1] * kr[d+1];
                s2 += q[d+2] * kr[d+2];
                s3 += q[d+3] * kr[d+3];
            }
            float s = (s0 + s1) + (s2 + s3) + srow[j];
            mx = fmaxf(mx, s);
            srow[j] = s;
        }
        // softmax (unnormalized exp in smem; fold 1/sum into epilogue)
        float sum = 0.f;
        for (int j = 0; j < NT; j++) {
            float e = __expf(srow[j] - mx);
            srow[j] = e;
            sum += e;
        }
        inv = 1.0f / sum;
    }
    __syncthreads();

    // Swap V into the K/V tile
    {
        const float4* src = (const float4*)(g_v + base);
        float4* dst = (float4*)sKV;
        for (int i = tid; i < NT * HD / 4; i += 160)
            dst[i] = src[i];
    }
    __syncthreads();

    if (tid < NT) {
        const float* srow = sS + tid * 145;
        float acc[HD];
#pragma unroll
        for (int d = 0; d < HD; d++) acc[d] = 0.f;
        for (int j = 0; j < NT; j++) {
            float pj = srow[j];
            const float* vr = sKV + j * HD;  // broadcast
#pragma unroll
            for (int d = 0; d < HD; d++)
                acc[d] += pj * vr[d];
        }
        // write (b, n, h, d) layout so out_gemm reads dense rows
        float4* o4 = (float4*)(g_ao + (b * NT + tid) * CD + h * HD);
#pragma unroll
        for (int d = 0; d < HD / 4; d++) {
            float4 t;
            t.x = acc[d*4+0] * inv;
            t.y = acc[d*4+1] * inv;
            t.z = acc[d*4+2] * inv;
            t.w = acc[d*4+3] * inv;
            o4[d] = t;
        }
    }
}

// ---------------------------------------------------------------------------
// Kernel 3: output projection.  out[36864,384] = AO[36864,384] @ Wout[384,384] + b
// Same double-buffered SGEMM skeleton as qkv_gemm.
// ---------------------------------------------------------------------------
__global__ __launch_bounds__(256) void out_gemm(const float* __restrict__ W,
                                                const float* __restrict__ bias,
                                                float* __restrict__ out)
{
    __shared__ float As[2][8][128];
    __shared__ float Bs[2][8][128];
    const int tid = threadIdx.x;
    const int m0 = blockIdx.y * 128;
    const int n0 = blockIdx.x * 128;
    const int tx = tid & 15, ty = tid >> 4;
    const int a_row = tid >> 1, a_col = (tid & 1) * 4;
    const int b_row = tid >> 5, b_col = (tid & 31) * 4;

    float acc[8][8];
#pragma unroll
    for (int i = 0; i < 8; i++)
#pragma unroll
        for (int j = 0; j < 8; j++) acc[i][j] = 0.f;

    const float* Ap = g_ao + (m0 + a_row) * CD + a_col;
    const float* Bp = W + b_row * CD + n0 + b_col;

    {
        float4 av = *(const float4*)(Ap);
        float4 bv = *(const float4*)(Bp);
        As[0][a_col+0][a_row] = av.x;
        As[0][a_col+1][a_row] = av.y;
        As[0][a_col+2][a_row] = av.z;
        As[0][a_col+3][a_row] = av.w;
        *(float4*)&Bs[0][b_row][b_col] = bv;
    }
    __syncthreads();

    int cur = 0;
    for (int k0 = 0; k0 < CD; k0 += 8) {
        float4 an, bn;
        const bool has_next = (k0 + 8 < CD);
        if (has_next) {
            an = *(const float4*)(Ap + (k0 + 8));
            bn = *(const float4*)(Bp + (k0 + 8) * CD);
        }
#pragma unroll
        for (int k = 0; k < 8; k++) {
            float ra[8], rb[8];
            *(float4*)&ra[0] = *(const float4*)&As[cur][k][ty*8];
            *(float4*)&ra[4] = *(const float4*)&As[cur][k][ty*8+4];
            *(float4*)&rb[0] = *(const float4*)&Bs[cur][k][tx*8];
            *(float4*)&rb[4] = *(const float4*)&Bs[cur][k][tx*8+4];
#pragma unroll
            for (int i = 0; i < 8; i++)
#pragma unroll
                for (int j = 0; j < 8; j++)
                    acc[i][j] += ra[i] * rb[j];
        }
        if (has_next) {
            int nxt = cur ^ 1;
            As[nxt][a_col+0][a_row] = an.x;
            As[nxt][a_col+1][a_row] = an.y;
            As[nxt][a_col+2][a_row] = an.z;
            As[nxt][a_col+3][a_row] = an.w;
            *(float4*)&Bs[nxt][b_row][b_col] = bn;
        }
        __syncthreads();
        cur ^= 1;
    }

    const int col0 = n0 + tx * 8;
#pragma unroll
    for (int i = 0; i < 8; i++) {
        int m = m0 + ty * 8 + i;
        float4* o4 = (float4*)(out + m * CD + col0);
        float4 v0, v1;
        v0.x = acc[i][0] + bias[col0+0];
        v0.y = acc[i][1] + bias[col0+1];
        v0.z = acc[i][2] + bias[col0+2];
        v0.w = acc[i][3] + bias[col0+3];
        v1.x = acc[i][4] + bias[col0+4];
        v1.y = acc[i][5] + bias[col0+5];
        v1.z = acc[i][6] + bias[col0+6];
        v1.w = acc[i][7] + bias[col0+7];
        o4[0] = v0;
        o4[1] = v1;
    }
}

// ---------------------------------------------------------------------------
extern "C" void kernel_launch(void* const* d_in, const int* in_sizes, int n_in,
                              void* d_out, int out_size)
{
    (void)in_sizes; (void)n_in; (void)out_size;
    const float* x     = (const float*)d_in[0];
    const float* mask  = (const float*)d_in[1];
    const float* w_qkv = (const float*)d_in[2];
    const float* b_qkv = (const float*)d_in[3];
    const float* w_out = (const float*)d_in[4];
    const float* b_out = (const float*)d_in[5];
    const float* table = (const float*)d_in[6];
    const int*   pidx  = (const int*)d_in[7];
    float* out = (float*)d_out;

    // Position-index pregather (tiny)
    pi_precompute<<<(8 * PIDX_LEN + 255) / 256, 256>>>(pidx);

    // QKV projection: grid (1152/128, 36864/128)
    qkv_gemm<<<dim3(9, 288), 256>>>(x, w_qkv, b_qkv);

    // Attention: one block per (head, window)
    const int shmem = (NT * 145 + NT * HD) * (int)sizeof(float);  // 101952 B
    cudaFuncSetAttribute(attn_kernel, cudaFuncAttributeMaxDynamicSharedMemorySize, shmem);
    attn_kernel<<<dim3(NH, NB), 160, shmem>>>(mask, table);

    // Output projection: grid (384/128, 36864/128)
    out_gemm<<<dim3(3, 288), 256>>>(w_out, b_out, out);
}

// round 16
// speedup vs baseline: 1.1868x; 1.0001x over previous
#include <cuda_runtime.h>

// Problem constants
#define NB   256          // windows (Bw)
#define NT   144          // tokens per window (N)
#define CD   384          // channel dim
#define NH   12           // heads
#define HD   32           // head dim
#define M_TOT (NB*NT)     // 36864 rows
#define QKV_N 1152
#define PIDX_LEN (NT*NT)  // 20736

// Scratch (static device allocations are the only legal scratch)
__device__ __align__(128) float g_q[NB*NH*NT*HD];
__device__ __align__(128) float g_k[NB*NH*NT*HD];
__device__ __align__(128) float g_v[NB*NH*NT*HD];
__device__ __align__(128) float g_ao[M_TOT*CD];
__device__ __align__(128) short g_pi16[8 * PIDX_LEN];   // per-r gathered position index

// ---------------------------------------------------------------------------
// Kernel 0: precompute g_pi16[r][ij] = pidx[(ij*8 + r) % 20736]  (fits int16)
// ---------------------------------------------------------------------------
__global__ void pi_precompute(const int* __restrict__ pidx)
{
    int idx = blockIdx.x * blockDim.x + threadIdx.x;
    if (idx >= 8 * PIDX_LEN) return;
    int r = idx / PIDX_LEN;
    int ij = idx - r * PIDX_LEN;
    int p = (ij * 8 + r) % PIDX_LEN;
    g_pi16[idx] = (short)pidx[p];
}

// ---------------------------------------------------------------------------
// Kernel 1: QKV projection.  C[36864,1152] = X[36864,384] @ W[384,1152] + b
// 128x128 block tile, BK=8 double-buffered, 8x8 per-thread microtile, 256 thr.
// Epilogue scatters into per-(window,head) Q/K/V layout; q gets *HD^-0.5.
// ---------------------------------------------------------------------------
__global__ __launch_bounds__(256) void qkv_gemm(const float* __restrict__ X,
                                                const float* __restrict__ W,
                                                const float* __restrict__ bias)
{
    __shared__ float As[2][8][128];
    __shared__ float Bs[2][8][128];
    const int tid = threadIdx.x;
    const int m0 = blockIdx.y * 128;
    const int n0 = blockIdx.x * 128;
    const int tx = tid & 15, ty = tid >> 4;
    const int a_row = tid >> 1, a_col = (tid & 1) * 4;
    const int b_row = tid >> 5, b_col = (tid & 31) * 4;

    float acc[8][8];
#pragma unroll
    for (int i = 0; i < 8; i++)
#pragma unroll
        for (int j = 0; j < 8; j++) acc[i][j] = 0.f;

    const float* Ap = X + (m0 + a_row) * CD + a_col;
    const float* Bp = W + b_row * QKV_N + n0 + b_col;

    // preload k0 = 0
    {
        float4 av = *(const float4*)(Ap);
        float4 bv = *(const float4*)(Bp);
        As[0][a_col+0][a_row] = av.x;
        As[0][a_col+1][a_row] = av.y;
        As[0][a_col+2][a_row] = av.z;
        As[0][a_col+3][a_row] = av.w;
        *(float4*)&Bs[0][b_row][b_col] = bv;
    }
    __syncthreads();

    int cur = 0;
    for (int k0 = 0; k0 < CD; k0 += 8) {
        float4 an, bn;
        const bool has_next = (k0 + 8 < CD);
        if (has_next) {
            an = *(const float4*)(Ap + (k0 + 8));
            bn = *(const float4*)(Bp + (k0 + 8) * QKV_N);
        }
#pragma unroll
        for (int k = 0; k < 8; k++) {
            float ra[8], rb[8];
            *(float4*)&ra[0] = *(const float4*)&As[cur][k][ty*8];
            *(float4*)&ra[4] = *(const float4*)&As[cur][k][ty*8+4];
            *(float4*)&rb[0] = *(const float4*)&Bs[cur][k][tx*8];
            *(float4*)&rb[4] = *(const float4*)&Bs[cur][k][tx*8+4];
#pragma unroll
            for (int i = 0; i < 8; i++)
#pragma unroll
                for (int j = 0; j < 8; j++)
                    acc[i][j] += ra[i] * rb[j];
        }
        if (has_next) {
            int nxt = cur ^ 1;
            As[nxt][a_col+0][a_row] = an.x;
            As[nxt][a_col+1][a_row] = an.y;
            As[nxt][a_col+2][a_row] = an.z;
            As[nxt][a_col+3][a_row] = an.w;
            *(float4*)&Bs[nxt][b_row][b_col] = bn;
        }
        __syncthreads();
        cur ^= 1;
    }

    // Epilogue: whole 128-col tile lives inside one of q/k/v (384 = 3*128).
    const int which = n0 / CD;                          // 0=q, 1=k, 2=v
    float* dst = (which == 0) ? g_q : ((which == 1) ? g_k : g_v);
    const float sc = (which == 0) ? 0.17677669529663689f : 1.0f;  // 32^-0.5
    const int seg_col = (n0 - which * CD) + tx * 8;     // column within segment
    const int hh = seg_col >> 5;                        // head
    const int dd = seg_col & 31;                        // head-dim base (multiple of 8)
#pragma unroll
    for (int i = 0; i < 8; i++) {
        int m = m0 + ty * 8 + i;
        int b = m / NT, nn = m - b * NT;
        float* o = dst + (((b * NH + hh) * NT) + nn) * HD + dd;
#pragma unroll
        for (int j = 0; j < 8; j++)
            o[j] = (acc[i][j] + bias[n0 + tx * 8 + j]) * sc;
    }
}

// ---------------------------------------------------------------------------
// Kernel 2: attention per (window b, head h).
// One CTA per (b,h). 160 threads; threads 0..143 each own one query row.
// Phase A (cooperative fill): sS[i][j] = mask(b&7,i,j) + table[pi(r,ij)][b&31][h]
//   - mask + g_pi16 loads are coalesced; table gather has ~130-deep MLP/thread.
// Phase B: per-row QK dot (K broadcast from smem) + running max.
// Phase C: softmax; Phase D: PV from smem-resident V.
// sS stride 145 -> bank (tid*17+j)%32, conflict-free scalar access.
// ---------------------------------------------------------------------------
__global__ __launch_bounds__(160) void attn_kernel(const float* __restrict__ mask,
                                                   const float* __restrict__ table)
{
    extern __shared__ float smem[];
    float* sS  = smem;                 // 144 * 145 floats
    float* sKV = smem + NT * 145;      // 144 * 32 floats

    const int tid = threadIdx.x;
    const int h = blockIdx.x;
    const int b = blockIdx.y;
    const int base = ((b * NH + h) * NT) * HD;

    // Load K tile cooperatively
    {
        const float4* src = (const float4*)(g_k + base);
        float4* dst = (float4*)sKV;
        for (int i = tid; i < NT * HD / 4; i += 160)
            dst[i] = src[i];
    }

    // Cooperative fill: mask + earth bias into sS
    {
        const int cc = (b & 31) * NH + h;
        const float* mbase = mask + (b & 7) * PIDX_LEN;
        const short* pis = g_pi16 + (b >> 5) * PIDX_LEN;
        for (int idx = tid; idx < PIDX_LEN; idx += 160) {
            int i = idx / NT;
            int j = idx - i * NT;
            int pi = (int)pis[idx];
            sS[i * 145 + j] = mbase[idx] + __ldg(table + pi * (32 * NH) + cc);
        }
    }

    // Load this thread's q row
    float q[HD];
    if (tid < NT) {
        const float4* qp = (const float4*)(g_q + base + tid * HD);
#pragma unroll
        for (int d = 0; d < HD / 4; d++) {
            float4 t = qp[d];
            q[d*4+0] = t.x; q[d*4+1] = t.y; q[d*4+2] = t.z; q[d*4+3] = t.w;
        }
    }
    __syncthreads();

    float inv = 0.f;
    if (tid < NT) {
        float* srow = sS + tid * 145;
        float mx = -1e30f;
        for (int j = 0; j < NT; j++) {
            const float* kr = sKV + j * HD;   // broadcast across threads
            float s0 = 0.f, s1 = 0.f, s2 = 0.f, s3 = 0.f;
#pragma unroll
            for (int d = 0; d < HD; d += 4) {
                s0 += q[d+0] * kr[d+0];
                s1 += q[d+1] * kr[d+1];
                s2 += q[d+2] * kr[d+2];
                s3 += q[d+3] * kr[d+3];
            }
            float s = (s0 + s1) + (s2 + s3) + srow[j];
            mx = fmaxf(mx, s);
            srow[j] = s;
        }
        // softmax (unnormalized exp in smem; fold 1/sum into epilogue)
        float sum = 0.f;
        for (int j = 0; j < NT; j++) {
            float e = __expf(srow[j] - mx);
            srow[j] = e;
            sum += e;
        }
        inv = 1.0f / sum;
    }
    __syncthreads();

    // Swap V into the K/V tile
    {
        const float4* src = (const float4*)(g_v + base);
        float4* dst = (float4*)sKV;
        for (int i = tid; i < NT * HD / 4; i += 160)
            dst[i] = src[i];
    }
    __syncthreads();

    if (tid < NT) {
        const float* srow = sS + tid * 145;
        float acc[HD];
#pragma unroll
        for (int d = 0; d < HD; d++) acc[d] = 0.f;
        for (int j = 0; j < NT; j++) {
            float pj = srow[j];
            const float* vr = sKV + j * HD;  // broadcast
#pragma unroll
            for (int d = 0; d < HD; d++)
                acc[d] += pj * vr[d];
        }
        // write (b, n, h, d) layout so out_gemm reads dense rows
        float4* o4 = (float4*)(g_ao + (b * NT + tid) * CD + h * HD);
#pragma unroll
        for (int d = 0; d < HD / 4; d++) {
            float4 t;
            t.x = acc[d*4+0] * inv;
            t.y = acc[d*4+1] * inv;
            t.z = acc[d*4+2] * inv;
            t.w = acc[d*4+3] * inv;
            o4[d] = t;
        }
    }
}

// ---------------------------------------------------------------------------
// Kernel 3: output projection.  out[36864,384] = AO[36864,384] @ Wout[384,384] + b
// Same double-buffered SGEMM skeleton as qkv_gemm.
// ---------------------------------------------------------------------------
__global__ __launch_bounds__(256) void out_gemm(const float* __restrict__ W,
                                                const float* __restrict__ bias,
                                                float* __restrict__ out)
{
    __shared__ float As[2][8][128];
    __shared__ float Bs[2][8][128];
    const int tid = threadIdx.x;
    const int m0 = blockIdx.y * 128;
    const int n0 = blockIdx.x * 128;
    const int tx = tid & 15, ty = tid >> 4;
    const int a_row = tid >> 1, a_col = (tid & 1) * 4;
    const int b_row = tid >> 5, b_col = (tid & 31) * 4;

    float acc[8][8];
#pragma unroll
    for (int i = 0; i < 8; i++)
#pragma unroll
        for (int j = 0; j < 8; j++) acc[i][j] = 0.f;

    const float* Ap = g_ao + (m0 + a_row) * CD + a_col;
    const float* Bp = W + b_row * CD + n0 + b_col;

    {
        float4 av = *(const float4*)(Ap);
        float4 bv = *(const float4*)(Bp);
        As[0][a_col+0][a_row] = av.x;
        As[0][a_col+1][a_row] = av.y;
        As[0][a_col+2][a_row] = av.z;
        As[0][a_col+3][a_row] = av.w;
        *(float4*)&Bs[0][b_row][b_col] = bv;
    }
    __syncthreads();

    int cur = 0;
    for (int k0 = 0; k0 < CD; k0 += 8) {
        float4 an, bn;
        const bool has_next = (k0 + 8 < CD);
        if (has_next) {
            an = *(const float4*)(Ap + (k0 + 8));
            bn = *(const float4*)(Bp + (k0 + 8) * CD);
        }
#pragma unroll
        for (int k = 0; k < 8; k++) {
            float ra[8], rb[8];
            *(float4*)&ra[0] = *(const float4*)&As[cur][k][ty*8];
            *(float4*)&ra[4] = *(const float4*)&As[cur][k][ty*8+4];
            *(float4*)&rb[0] = *(const float4*)&Bs[cur][k][tx*8];
            *(float4*)&rb[4] = *(const float4*)&Bs[cur][k][tx*8+4];
#pragma unroll
            for (int i = 0; i < 8; i++)
#pragma unroll
                for (int j = 0; j < 8; j++)
                    acc[i][j] += ra[i] * rb[j];
        }
        if (has_next) {
            int nxt = cur ^ 1;
            As[nxt][a_col+0][a_row] = an.x;
            As[nxt][a_col+1][a_row] = an.y;
            As[nxt][a_col+2][a_row] = an.z;
            As[nxt][a_col+3][a_row] = an.w;
            *(float4*)&Bs[nxt][b_row][b_col] = bn;
        }
        __syncthreads();
        cur ^= 1;
    }

    const int col0 = n0 + tx * 8;
#pragma unroll
    for (int i = 0; i < 8; i++) {
        int m = m0 + ty * 8 + i;
        float4* o4 = (float4*)(out + m * CD + col0);
        float4 v0, v1;
        v0.x = acc[i][0] + bias[col0+0];
        v0.y = acc[i][1] + bias[col0+1];
        v0.z = acc[i][2] + bias[col0+2];
        v0.w = acc[i][3] + bias[col0+3];
        v1.x = acc[i][4] + bias[col0+4];
        v1.y = acc[i][5] + bias[col0+5];
        v1.z = acc[i][6] + bias[col0+6];
        v1.w = acc[i][7] + bias[col0+7];
        o4[0] = v0;
        o4[1] = v1;
    }
}

// ---------------------------------------------------------------------------
extern "C" void kernel_launch(void* const* d_in, const int* in_sizes, int n_in,
                              void* d_out, int out_size)
{
    (void)in_sizes; (void)n_in; (void)out_size;
    const float* x     = (const float*)d_in[0];
    const float* mask  = (const float*)d_in[1];
    const float* w_qkv = (const float*)d_in[2];
    const float* b_qkv = (const float*)d_in[3];
    const float* w_out = (const float*)d_in[4];
    const float* b_out = (const float*)d_in[5];
    const float* table = (const float*)d_in[6];
    const int*   pidx  = (const int*)d_in[7];
    float* out = (float*)d_out;

    // Position-index pregather (tiny)
    pi_precompute<<<(8 * PIDX_LEN + 255) / 256, 256>>>(pidx);

    // QKV projection: grid (1152/128, 36864/128)
    qkv_gemm<<<dim3(9, 288), 256>>>(x, w_qkv, b_qkv);

    // Attention: one block per (head, window)
    const int shmem = (NT * 145 + NT * HD) * (int)sizeof(float);  // 101952 B
    cudaFuncSetAttribute(attn_kernel, cudaFuncAttributeMaxDynamicSharedMemorySize, shmem);
    attn_kernel<<<dim3(NH, NB), 160, shmem>>>(mask, table);

    // Output projection: grid (384/128, 36864/128)
    out_gemm<<<dim3(3, 288), 256>>>(w_out, b_out, out);
}

// round 17
// speedup vs baseline: 1.3516x; 1.1389x over previous
#include <cuda_runtime.h>
#include <cuda_fp16.h>

// Problem constants
#define NB   256          // windows (Bw)
#define NT   144          // tokens per window (N)
#define CD   384          // channel dim
#define NH   12           // heads
#define HD   32           // head dim
#define M_TOT (NB*NT)     // 36864 rows
#define QKV_N 1152
#define PIDX_LEN (NT*NT)  // 20736
#define TABLE_ROWS 3312

// Scratch (static device allocations are the only legal scratch)
__device__ __align__(128) float g_q[NB*NH*NT*HD];
__device__ __align__(128) float g_k[NB*NH*NT*HD];
__device__ __align__(128) float g_v[NB*NH*NT*HD];
__device__ __align__(128) float g_ao[M_TOT*CD];
__device__ __align__(128) short g_pi16[8 * PIDX_LEN];   // per-r gathered position index

// ---------------------------------------------------------------------------
// Kernel 0: precompute g_pi16[r][ij] = pidx[(ij*8 + r) % 20736]  (fits int16)
// ---------------------------------------------------------------------------
__global__ void pi_precompute(const int* __restrict__ pidx)
{
    int idx = blockIdx.x * blockDim.x + threadIdx.x;
    if (idx >= 8 * PIDX_LEN) return;
    int r = idx / PIDX_LEN;
    int ij = idx - r * PIDX_LEN;
    int p = (ij * 8 + r) % PIDX_LEN;
    g_pi16[idx] = (short)pidx[p];
}

// ---------------------------------------------------------------------------
// Kernel 1: QKV projection.  C[36864,1152] = X[36864,384] @ W[384,1152] + b
// 128x128 block tile, BK=8 double-buffered, 8x8 per-thread microtile, 256 thr.
// Epilogue scatters into per-(window,head) Q/K/V layout; q gets *HD^-0.5.
// ---------------------------------------------------------------------------
__global__ __launch_bounds__(256) void qkv_gemm(const float* __restrict__ X,
                                                const float* __restrict__ W,
                                                const float* __restrict__ bias)
{
    __shared__ float As[2][8][128];
    __shared__ float Bs[2][8][128];
    const int tid = threadIdx.x;
    const int m0 = blockIdx.y * 128;
    const int n0 = blockIdx.x * 128;
    const int tx = tid & 15, ty = tid >> 4;
    const int a_row = tid >> 1, a_col = (tid & 1) * 4;
    const int b_row = tid >> 5, b_col = (tid & 31) * 4;

    float acc[8][8];
#pragma unroll
    for (int i = 0; i < 8; i++)
#pragma unroll
        for (int j = 0; j < 8; j++) acc[i][j] = 0.f;

    const float* Ap = X + (m0 + a_row) * CD + a_col;
    const float* Bp = W + b_row * QKV_N + n0 + b_col;

    // preload k0 = 0
    {
        float4 av = *(const float4*)(Ap);
        float4 bv = *(const float4*)(Bp);
        As[0][a_col+0][a_row] = av.x;
        As[0][a_col+1][a_row] = av.y;
        As[0][a_col+2][a_row] = av.z;
        As[0][a_col+3][a_row] = av.w;
        *(float4*)&Bs[0][b_row][b_col] = bv;
    }
    __syncthreads();

    int cur = 0;
    for (int k0 = 0; k0 < CD; k0 += 8) {
        float4 an, bn;
        const bool has_next = (k0 + 8 < CD);
        if (has_next) {
            an = *(const float4*)(Ap + (k0 + 8));
            bn = *(const float4*)(Bp + (k0 + 8) * QKV_N);
        }
#pragma unroll
        for (int k = 0; k < 8; k++) {
            float ra[8], rb[8];
            *(float4*)&ra[0] = *(const float4*)&As[cur][k][ty*8];
            *(float4*)&ra[4] = *(const float4*)&As[cur][k][ty*8+4];
            *(float4*)&rb[0] = *(const float4*)&Bs[cur][k][tx*8];
            *(float4*)&rb[4] = *(const float4*)&Bs[cur][k][tx*8+4];
#pragma unroll
            for (int i = 0; i < 8; i++)
#pragma unroll
                for (int j = 0; j < 8; j++)
                    acc[i][j] += ra[i] * rb[j];
        }
        if (has_next) {
            int nxt = cur ^ 1;
            As[nxt][a_col+0][a_row] = an.x;
            As[nxt][a_col+1][a_row] = an.y;
            As[nxt][a_col+2][a_row] = an.z;
            As[nxt][a_col+3][a_row] = an.w;
            *(float4*)&Bs[nxt][b_row][b_col] = bn;
        }
        __syncthreads();
        cur ^= 1;
    }

    // Epilogue: whole 128-col tile lives inside one of q/k/v (384 = 3*128).
    const int which = n0 / CD;                          // 0=q, 1=k, 2=v
    float* dst = (which == 0) ? g_q : ((which == 1) ? g_k : g_v);
    const float sc = (which == 0) ? 0.17677669529663689f : 1.0f;  // 32^-0.5
    const int seg_col = (n0 - which * CD) + tx * 8;     // column within segment
    const int hh = seg_col >> 5;                        // head
    const int dd = seg_col & 31;                        // head-dim base (multiple of 8)
#pragma unroll
    for (int i = 0; i < 8; i++) {
        int m = m0 + ty * 8 + i;
        int b = m / NT, nn = m - b * NT;
        float* o = dst + (((b * NH + hh) * NT) + nn) * HD + dd;
#pragma unroll
        for (int j = 0; j < 8; j++)
            o[j] = (acc[i][j] + bias[n0 + tx * 8 + j]) * sc;
    }
}

// ---------------------------------------------------------------------------
// Kernel 2: attention per (window b, head h).
// One CTA per (b,h). 160 threads; threads 0..143 each own one query row.
// Stage 0: cache K tile AND the live table slice table[:, b&31, h] (3312
//          values) in SMEM as half — the only part of the 5MB table this CTA
//          touches. 63x fewer gather wavefronts vs per-element global gathers.
// Stage 1 (coop fill): sS[i][j] = mask(b&7,i,j) + sTab[pi16(r,ij)]
//          (mask/pi16 LDGs coalesced; table gather is now a cheap LDS).
// Stage 2: per-row QK dot (K broadcast from smem) + running max.
// Stage 3: softmax; Stage 4: PV from smem-resident V.
// smem total ~108.6KB -> 2 CTAs/SM (10 warps) for latency hiding.
// sS stride 145 -> conflict-free row access.
// ---------------------------------------------------------------------------
#define SS_OFF   0
#define STAB_OFF (NT * 145)                    // floats: 20880
#define SKV_OFF  (STAB_OFF + (TABLE_ROWS+16)/2 + 8)   // half array in float units

__global__ __launch_bounds__(160) void attn_kernel(const float* __restrict__ mask,
                                                   const float* __restrict__ table)
{
    extern __shared__ float smem[];
    float* sS   = smem;                        // 144*145 floats
    __half* sTab = (__half*)(smem + STAB_OFF); // 3312 halves
    float* sKV  = smem + SKV_OFF;              // 144*32 floats

    const int tid = threadIdx.x;
    const int h = blockIdx.x;
    const int b = blockIdx.y;
    const int base = ((b * NH + h) * NT) * HD;
    const int cc = (b & 31) * NH + h;

    // Stage 0: K tile + table slice
    {
        const float4* src = (const float4*)(g_k + base);
        float4* dst = (float4*)sKV;
        for (int i = tid; i < NT * HD / 4; i += 160)
            dst[i] = src[i];
        const float* tslice = table + cc;
        for (int t = tid; t < TABLE_ROWS; t += 160)
            sTab[t] = __float2half(tslice[t * (32 * NH)]);
    }
    __syncthreads();

    // Stage 1: cooperative fill of mask + earth bias
    {
        const float* mbase = mask + (b & 7) * PIDX_LEN;
        const short* pis = g_pi16 + (b >> 5) * PIDX_LEN;
        for (int idx = tid; idx < PIDX_LEN; idx += 160) {
            int i = idx / NT;
            int j = idx - i * NT;
            int pi = (int)pis[idx];
            sS[i * 145 + j] = mbase[idx] + __half2float(sTab[pi]);
        }
    }

    // Load this thread's q row
    float q[HD];
    if (tid < NT) {
        const float4* qp = (const float4*)(g_q + base + tid * HD);
#pragma unroll
        for (int d = 0; d < HD / 4; d++) {
            float4 t = qp[d];
            q[d*4+0] = t.x; q[d*4+1] = t.y; q[d*4+2] = t.z; q[d*4+3] = t.w;
        }
    }
    __syncthreads();

    float inv = 0.f;
    if (tid < NT) {
        float* srow = sS + tid * 145;
        float mx = -1e30f;
        for (int j = 0; j < NT; j++) {
            const float* kr = sKV + j * HD;   // broadcast across threads
            float s0 = 0.f, s1 = 0.f, s2 = 0.f, s3 = 0.f;
#pragma unroll
            for (int d = 0; d < HD; d += 4) {
                s0 += q[d+0] * kr[d+0];
                s1 += q[d+1] * kr[d+1];
                s2 += q[d+2] * kr[d+2];
                s3 += q[d+3] * kr[d+3];
            }
            float s = (s0 + s1) + (s2 + s3) + srow[j];
            mx = fmaxf(mx, s);
            srow[j] = s;
        }
        // softmax (unnormalized exp in smem; fold 1/sum into epilogue)
        float sum = 0.f;
        for (int j = 0; j < NT; j++) {
            float e = __expf(srow[j] - mx);
            srow[j] = e;
            sum += e;
        }
        inv = 1.0f / sum;
    }
    __syncthreads();

    // Swap V into the K/V tile
    {
        const float4* src = (const float4*)(g_v + base);
        float4* dst = (float4*)sKV;
        for (int i = tid; i < NT * HD / 4; i += 160)
            dst[i] = src[i];
    }
    __syncthreads();

    if (tid < NT) {
        const float* srow = sS + tid * 145;
        float acc[HD];
#pragma unroll
        for (int d = 0; d < HD; d++) acc[d] = 0.f;
        for (int j = 0; j < NT; j++) {
            float pj = srow[j];
            const float* vr = sKV + j * HD;  // broadcast
#pragma unroll
            for (int d = 0; d < HD; d++)
                acc[d] += pj * vr[d];
        }
        // write (b, n, h, d) layout so out_gemm reads dense rows
        float4* o4 = (float4*)(g_ao + (b * NT + tid) * CD + h * HD);
#pragma unroll
        for (int d = 0; d < HD / 4; d++) {
            float4 t;
            t.x = acc[d*4+0] * inv;
            t.y = acc[d*4+1] * inv;
            t.z = acc[d*4+2] * inv;
            t.w = acc[d*4+3] * inv;
            o4[d] = t;
        }
    }
}

// ---------------------------------------------------------------------------
// Kernel 3: output projection.  out[36864,384] = AO[36864,384] @ Wout[384,384] + b
// Same double-buffered SGEMM skeleton as qkv_gemm.
// ---------------------------------------------------------------------------
__global__ __launch_bounds__(256) void out_gemm(const float* __restrict__ W,
                                                const float* __restrict__ bias,
                                                float* __restrict__ out)
{
    __shared__ float As[2][8][128];
    __shared__ float Bs[2][8][128];
    const int tid = threadIdx.x;
    const int m0 = blockIdx.y * 128;
    const int n0 = blockIdx.x * 128;
    const int tx = tid & 15, ty = tid >> 4;
    const int a_row = tid >> 1, a_col = (tid & 1) * 4;
    const int b_row = tid >> 5, b_col = (tid & 31) * 4;

    float acc[8][8];
#pragma unroll
    for (int i = 0; i < 8; i++)
#pragma unroll
        for (int j = 0; j < 8; j++) acc[i][j] = 0.f;

    const float* Ap = g_ao + (m0 + a_row) * CD + a_col;
    const float* Bp = W + b_row * CD + n0 + b_col;

    {
        float4 av = *(const float4*)(Ap);
        float4 bv = *(const float4*)(Bp);
        As[0][a_col+0][a_row] = av.x;
        As[0][a_col+1][a_row] = av.y;
        As[0][a_col+2][a_row] = av.z;
        As[0][a_col+3][a_row] = av.w;
        *(float4*)&Bs[0][b_row][b_col] = bv;
    }
    __syncthreads();

    int cur = 0;
    for (int k0 = 0; k0 < CD; k0 += 8) {
        float4 an, bn;
        const bool has_next = (k0 + 8 < CD);
        if (has_next) {
            an = *(const float4*)(Ap + (k0 + 8));
            bn = *(const float4*)(Bp + (k0 + 8) * CD);
        }
#pragma unroll
        for (int k = 0; k < 8; k++) {
            float ra[8], rb[8];
            *(float4*)&ra[0] = *(const float4*)&As[cur][k][ty*8];
            *(float4*)&ra[4] = *(const float4*)&As[cur][k][ty*8+4];
            *(float4*)&rb[0] = *(const float4*)&Bs[cur][k][tx*8];
            *(float4*)&rb[4] = *(const float4*)&Bs[cur][k][tx*8+4];
#pragma unroll
            for (int i = 0; i < 8; i++)
#pragma unroll
                for (int j = 0; j < 8; j++)
                    acc[i][j] += ra[i] * rb[j];
        }
        if (has_next) {
            int nxt = cur ^ 1;
            As[nxt][a_col+0][a_row] = an.x;
            As[nxt][a_col+1][a_row] = an.y;
            As[nxt][a_col+2][a_row] = an.z;
            As[nxt][a_col+3][a_row] = an.w;
            *(float4*)&Bs[nxt][b_row][b_col] = bn;
        }
        __syncthreads();
        cur ^= 1;
    }

    const int col0 = n0 + tx * 8;
#pragma unroll
    for (int i = 0; i < 8; i++) {
        int m = m0 + ty * 8 + i;
        float4* o4 = (float4*)(out + m * CD + col0);
        float4 v0, v1;
        v0.x = acc[i][0] + bias[col0+0];
        v0.y = acc[i][1] + bias[col0+1];
        v0.z = acc[i][2] + bias[col0+2];
        v0.w = acc[i][3] + bias[col0+3];
        v1.x = acc[i][4] + bias[col0+4];
        v1.y = acc[i][5] + bias[col0+5];
        v1.z = acc[i][6] + bias[col0+6];
        v1.w = acc[i][7] + bias[col0+7];
        o4[0] = v0;
        o4[1] = v1;
    }
}

// ---------------------------------------------------------------------------
extern "C" void kernel_launch(void* const* d_in, const int* in_sizes, int n_in,
                              void* d_out, int out_size)
{
    (void)in_sizes; (void)n_in; (void)out_size;
    const float* x     = (const float*)d_in[0];
    const float* mask  = (const float*)d_in[1];
    const float* w_qkv = (const float*)d_in[2];
    const float* b_qkv = (const float*)d_in[3];
    const float* w_out = (const float*)d_in[4];
    const float* b_out = (const float*)d_in[5];
    const float* table = (const float*)d_in[6];
    const int*   pidx  = (const int*)d_in[7];
    float* out = (float*)d_out;

    // Position-index pregather (tiny)
    pi_precompute<<<(8 * PIDX_LEN + 255) / 256, 256>>>(pidx);

    // QKV projection: grid (1152/128, 36864/128)
    qkv_gemm<<<dim3(9, 288), 256>>>(x, w_qkv, b_qkv);

    // Attention: one block per (head, window).
    // smem: sS (144*145 f32) + sTab (3312 half, padded) + sKV (144*32 f32)
    const int shmem = (SKV_OFF + NT * HD) * (int)sizeof(float);   // ~108.6 KB
    cudaFuncSetAttribute(attn_kernel, cudaFuncAttributeMaxDynamicSharedMemorySize, shmem);
    attn_kernel<<<dim3(NH, NB), 160, shmem>>>(mask, table);

    // Output projection: grid (384/128, 36864/128)
    out_gemm<<<dim3(3, 288), 256>>>(w_out, b_out, out);
}